// round 1
// baseline (speedup 1.0000x reference)
#include <cuda_runtime.h>
#include <cstdint>

// Problem constants
#define BB 256
#define CC 2048
#define HWN 49
#define KK 16

// Intermediate: BN'd, (1/49)-scaled featcov16, layout [b][k*49+hw]
__device__ float g_fc16[BB * 784];

// ---- f32x2 helpers (sm_103a packed fp32 FMA; 2x FFMA throughput) ----
__device__ __forceinline__ unsigned long long ffma2(unsigned long long a,
                                                    unsigned long long b,
                                                    unsigned long long c) {
    unsigned long long d;
    asm("fma.rn.f32x2 %0, %1, %2, %3;" : "=l"(d) : "l"(a), "l"(b), "l"(c));
    return d;
}
__device__ __forceinline__ unsigned long long pack2(float x, float y) {
    unsigned long long r;
    asm("mov.b64 %0, {%1, %2};" : "=l"(r) : "f"(x), "f"(y));
    return r;
}
__device__ __forceinline__ void unpack2(unsigned long long v, float& x, float& y) {
    asm("mov.b64 {%0, %1}, %2;" : "=f"(x), "=f"(y) : "l"(v));
}

// ============================================================================
// Kernel 1: fc16[b,k,hw] = BN( sum_c w16[k,c] * fm[b,c,hw] ) * (1/49)
// Block per b, 256 threads (8 warps). lanes = hw (hw and hw+32 per lane).
// C processed in 8 chunks of 256; warp w owns 32 c's of each chunk.
// w16 chunk staged transposed [c][18-pad] so adjacent-k pairs load as LDS.64.
// Cross-warp reduction through smem, BN + 1/49 folded at the store.
// ============================================================================
__global__ __launch_bounds__(256) void sam_conv_bn_kernel(
    const float* __restrict__ fm, const float* __restrict__ w16,
    const float* __restrict__ bng, const float* __restrict__ bnb,
    const float* __restrict__ bnm, const float* __restrict__ bnv) {
    __shared__ float wts[256 * 18];   // [c_local][18] (k in 0..15, pad to 18)
    __shared__ float red[8 * 784];    // per-warp partials
    __shared__ float invs[16], offs[16];

    const int b = blockIdx.x;
    const int tid = threadIdx.x;
    const int lane = tid & 31;
    const int wid = tid >> 5;

    if (tid < 16) {
        float iv = bng[tid] * rsqrtf(bnv[tid] + 1e-5f);
        invs[tid] = iv * (1.0f / 49.0f);
        offs[tid] = (bnb[tid] - bnm[tid] * iv) * (1.0f / 49.0f);
    }

    const float* fmb = fm + (size_t)b * (CC * HWN);

    unsigned long long acc0[8], acc1[8];
#pragma unroll
    for (int i = 0; i < 8; i++) { acc0[i] = 0ull; acc1[i] = 0ull; }

    for (int ch = 0; ch < 8; ch++) {
        const int cbase = ch * 256;
        // stage w16 chunk transposed: wts[c][k]
        for (int idx = tid; idx < 4096; idx += 256) {
            int k = idx >> 8;
            int c = idx & 255;
            wts[c * 18 + k] = w16[k * CC + cbase + c];
        }
        __syncthreads();

        const float* fmc = fmb + (size_t)(cbase + wid * 32) * HWN;
        const float* wrow = &wts[(wid * 32) * 18];
#pragma unroll 4
        for (int j = 0; j < 32; j++) {
            float v0 = fmc[j * HWN + lane];
            float v1 = (lane < 17) ? fmc[j * HWN + lane + 32] : 0.0f;
            unsigned long long vv0 = pack2(v0, v0);
            unsigned long long vv1 = pack2(v1, v1);
            const float* wr = wrow + j * 18;
#pragma unroll
            for (int kp = 0; kp < 8; kp++) {
                unsigned long long wp =
                    *(const unsigned long long*)(wr + 2 * kp);  // LDS.64 (k pair)
                acc0[kp] = ffma2(wp, vv0, acc0[kp]);
                acc1[kp] = ffma2(wp, vv1, acc1[kp]);
            }
        }
        __syncthreads();
    }

    // write per-warp partials
#pragma unroll
    for (int kp = 0; kp < 8; kp++) {
        float a, c0;
        unpack2(acc0[kp], a, c0);
        red[wid * 784 + (2 * kp) * 49 + lane] = a;
        red[wid * 784 + (2 * kp + 1) * 49 + lane] = c0;
        if (lane < 17) {
            float x, y;
            unpack2(acc1[kp], x, y);
            red[wid * 784 + (2 * kp) * 49 + lane + 32] = x;
            red[wid * 784 + (2 * kp + 1) * 49 + lane + 32] = y;
        }
    }
    __syncthreads();

    // reduce 8 warps, apply BN (+1/49), store
    for (int o = tid; o < 784; o += 256) {
        float s = 0.0f;
#pragma unroll
        for (int w = 0; w < 8; w++) s += red[w * 784 + o];
        int k = o / 49;
        g_fc16[b * 784 + o] = s * invs[k] + offs[k];
    }
}

// ============================================================================
// Kernel 2: out[b, k*2048 + c] = sum_hw fc16[b,k,hw] * fm[b,c,hw]
// Block per (c-tile of 224, b). Thread = one c. featmap tile staged
// contiguously into smem (column reads stride 49 floats -> conflict-free).
// fc16 staged [hw][16] so adjacent-k pairs are broadcast LDS.64.
// ============================================================================
__global__ __launch_bounds__(224) void sam_bilinear_kernel(
    const float* __restrict__ fm, float* __restrict__ out) {
    __shared__ float fms[224 * 49];
    __shared__ float fcs[784];  // [hw][16]

    const int tid = threadIdx.x;
    const int b = blockIdx.y;
    const int ct = blockIdx.x;
    const int cbase = ct * 224;
    const int ccount = min(224, CC - cbase);

    const float* fmb = fm + (size_t)b * (CC * HWN) + (size_t)cbase * HWN;

    for (int idx = tid; idx < 784; idx += 224) {
        int k = idx / 49;
        int hw = idx - k * 49;
        fcs[hw * 16 + k] = g_fc16[b * 784 + idx];
    }
    const int n4 = (ccount * HWN) >> 2;  // always exact multiple of 4
    for (int i = tid; i < n4; i += 224)
        ((float4*)fms)[i] = ((const float4*)fmb)[i];
    __syncthreads();

    if (tid < ccount) {
        unsigned long long acc[8];
#pragma unroll
        for (int i = 0; i < 8; i++) acc[i] = 0ull;
        const float* row = &fms[tid * 49];
#pragma unroll
        for (int hw = 0; hw < 49; hw++) {
            float v = row[hw];
            unsigned long long vv = pack2(v, v);
            const float* fr = &fcs[hw * 16];
#pragma unroll
            for (int kp = 0; kp < 8; kp++)
                acc[kp] = ffma2(*(const unsigned long long*)(fr + 2 * kp), vv,
                                acc[kp]);
        }
        float* ob = out + (size_t)b * 32768 + cbase + tid;
#pragma unroll
        for (int kp = 0; kp < 8; kp++) {
            float x, y;
            unpack2(acc[kp], x, y);
            ob[(2 * kp) * 2048] = x;
            ob[(2 * kp + 1) * 2048] = y;
        }
    }
}

extern "C" void kernel_launch(void* const* d_in, const int* in_sizes, int n_in,
                              void* d_out, int out_size) {
    const float* fm  = (const float*)d_in[0];  // featmap [256,2048,7,7]
    const float* w16 = (const float*)d_in[1];  // [16,2048]
    const float* bng = (const float*)d_in[2];
    const float* bnb = (const float*)d_in[3];
    const float* bnm = (const float*)d_in[4];
    const float* bnv = (const float*)d_in[5];
    float* out = (float*)d_out;                // [256, 32768]

    sam_conv_bn_kernel<<<BB, 256>>>(fm, w16, bng, bnb, bnm, bnv);
    dim3 g2(10, BB);  // ceil(2048/224) = 10 c-tiles
    sam_bilinear_kernel<<<g2, 224>>>(fm, out);
}